// round 7
// baseline (speedup 1.0000x reference)
#include <cuda_runtime.h>
#include <cstdint>
#include <cstddef>

// Problem constants
#define BATCH   64
#define CPB     3072           // anchors*H*W per batch (3*32*32)
#define CELLS   (BATCH*CPB)    // 196608
#define KSEL    100
#define NPAIR   (BATCH*KSEL)   // 6400
#define PCHUNK  800            // preds per IoU chunk (8 chunks)
#define NIOUB   (NPAIR/128)    // 50 iou blocks in x
#define NPSB    25             // pairsum grid dim (25x25)

// ---------------- scratch (device globals; no allocation) ----------------
__device__ float4 g_p4[NPAIR];        // selected pred corners
__device__ float  g_pa[NPAIR];        // pred areas
__device__ float4 g_t4[NPAIR];        // fixed target corners
__device__ float  g_topv[NPAIR];      // selected confidences
__device__ int    g_miou[NPAIR];      // max IoU per target (float bits, >=0)
__device__ float  g_diou[NPAIR];
__device__ unsigned int g_keys[CELLS]; // order-preserving conf-logit keys
__device__ float  g_negp[CELLS/256];  // 768 negpen partials
__device__ float  g_sl1p[NIOUB];      // 50 smooth-l1 partials
__device__ float  g_pairp[NPSB*NPSB]; // 625 pair partials
__device__ int    g_ctr;              // last-block counter (self-resetting)

// ---------------- helpers ----------------
__device__ __forceinline__ float rcp_approx(float x) {
    float y; asm("rcp.approx.f32 %0, %1;" : "=f"(y) : "f"(x)); return y;
}
__device__ __forceinline__ float sqrt_approx(float x) {
    float y; asm("sqrt.approx.f32 %0, %1;" : "=f"(y) : "f"(x)); return y;
}
__device__ __forceinline__ float sigmoidf_(float x) {
    return 1.0f / (1.0f + expf(-x));
}

// full-block float sum, result valid in thread 0 (NW warps)
template<int NW>
__device__ __forceinline__ float block_sum(float v) {
    __shared__ float sh[NW];
    #pragma unroll
    for (int o = 16; o > 0; o >>= 1) v += __shfl_down_sync(0xffffffffu, v, o);
    int lane = threadIdx.x & 31, wid = threadIdx.x >> 5;
    if (lane == 0) sh[wid] = v;
    __syncthreads();
    float s = 0.0f;
    if (wid == 0) {
        s = (lane < NW) ? sh[lane] : 0.0f;
        #pragma unroll
        for (int o = NW / 2; o > 0; o >>= 1) s += __shfl_down_sync(0xffffffffu, s, o);
    }
    __syncthreads();   // safe reuse of sh by later calls
    return s;
}

// ---------------- kernels ----------------

// Streaming pass over pred: build conf keys + negpen partials (coalesced
// float4 via smem). Blocks < 25 also fix targets + init miou.
__global__ void k_pre(const float* __restrict__ pred, const float* __restrict__ tgt) {
    __shared__ float4 buf[320];
    int blk = blockIdx.x, tid = threadIdx.x;
    const float4* src = (const float4*)pred + (size_t)blk * 320;
    #pragma unroll 2
    for (int i = tid; i < 320; i += 256) buf[i] = src[i];
    __syncthreads();
    const float* f = (const float*)buf;
    float pw = f[tid * 5 + 2], ph = f[tid * 5 + 3], cl = f[tid * 5 + 4];
    float neg = fmaxf(1.0f - pw, 0.0f) + fmaxf(1.0f - ph, 0.0f);
    unsigned int u = __float_as_uint(cl);
    u = (u & 0x80000000u) ? ~u : (u | 0x80000000u);   // order-preserving
    g_keys[blk * 256 + tid] = u;
    float tot = block_sum<8>(neg);
    if (tid == 0) g_negp[blk] = tot;

    if (blk < 25) {   // fused target fix + miou init (j < 6400)
        int j = blk * 256 + tid;
        g_miou[j] = 0;
        const float* t = tgt + (size_t)j * 4;
        float a = t[0], b = t[1], c = t[2], d = t[3];
        float x1 = fminf(a, c), x2 = fmaxf(a, c);
        float y1 = fminf(b, d), y2 = fmaxf(b, d);
        if (x1 == x2) x2 = x1 + 1.0f;
        if (y1 == y2) y2 = y1 + 1.0f;
        g_t4[j] = make_float4(x1, y1, x2, y2);
    }
}

// per-batch top-100: radix-select (12-bit hist on keys) + bitonic sort of
// candidates; ties -> smaller index via index complement in low 32 bits.
__global__ void k_topk(const float* __restrict__ pred) {
    __shared__ unsigned int hist[4096];
    __shared__ unsigned long long cand[512];
    __shared__ unsigned int tsum[256];
    __shared__ unsigned int safter[256];
    __shared__ unsigned int s_cnt, s_pivot;

    int b = blockIdx.x;
    int tid = threadIdx.x;
    const unsigned int* kb = g_keys + (size_t)b * CPB;

    for (int i = tid; i < 4096; i += 256) hist[i] = 0;
    if (tid == 0) s_cnt = 0;
    __syncthreads();

    #pragma unroll 4
    for (int s = tid; s < CPB; s += 256)
        atomicAdd(&hist[kb[s] >> 20], 1u);
    __syncthreads();

    // suffix counts over 4096 buckets (16 per thread)
    unsigned int mysum = 0;
    #pragma unroll
    for (int q = 0; q < 16; q++) mysum += hist[tid * 16 + q];
    tsum[tid] = mysum;
    __syncthreads();
    if (tid == 0) {
        unsigned int acc = 0;
        for (int t = 255; t >= 0; t--) { safter[t] = acc; acc += tsum[t]; }
    }
    __syncthreads();

    // pivot = max bucket with suffix-count >= KSEL (exactly one thread finds it)
    {
        unsigned int run = safter[tid];
        for (int q = 15; q >= 0; q--) {
            unsigned int c = hist[tid * 16 + q];
            run += c;
            if (run >= KSEL && (run - c) < KSEL) s_pivot = tid * 16 + q;
        }
    }
    __syncthreads();
    unsigned int piv = s_pivot;

    // gather candidates (all buckets >= pivot)
    #pragma unroll 4
    for (int s = tid; s < CPB; s += 256) {
        unsigned int u = kb[s];
        if ((u >> 20) >= piv) {
            unsigned int pos = atomicAdd(&s_cnt, 1u);
            if (pos < 512)
                cand[pos] = ((unsigned long long)u << 32) |
                            (unsigned long long)(0xFFFFFFFFu - (unsigned int)s);
        }
    }
    __syncthreads();
    unsigned int cnt = s_cnt; if (cnt > 512) cnt = 512;
    for (int i = tid; i < 512; i += 256) if (i >= (int)cnt) cand[i] = 0ull;

    // bitonic sort 512, descending
    for (unsigned int k = 2; k <= 512; k <<= 1) {
        for (unsigned int j = k >> 1; j > 0; j >>= 1) {
            __syncthreads();
            #pragma unroll 2
            for (int i = tid; i < 512; i += 256) {
                unsigned int ixj = (unsigned int)i ^ j;
                if (ixj > (unsigned int)i) {
                    unsigned long long a = cand[i], c2 = cand[ixj];
                    bool up = (((unsigned int)i & k) == 0);
                    if ((a < c2) == up) { cand[i] = c2; cand[ixj] = a; }
                }
            }
        }
    }
    __syncthreads();

    // winners -> postprocessed pred corners
    if (tid < KSEL) {
        unsigned long long m = cand[tid];
        int idx = (int)(0xFFFFFFFFu - (unsigned int)(m & 0xFFFFFFFFull));
        int j = b * KSEL + tid;
        const float* p = pred + (size_t)b * CPB * 5 + (size_t)idx * 5;
        float x = (sigmoidf_(p[0]) + (float)(idx & 31)) * 32.0f;         // + cx, *STRIDE
        float y = (sigmoidf_(p[1]) + (float)((idx >> 5) & 31)) * 32.0f;  // + cy
        float hw = expf(p[2]) * 32.0f * 0.5f;
        float hh = expf(p[3]) * 32.0f * 0.5f;
        float x1 = x - hw, y1 = y - hh, x2 = x + hw, y2 = y + hh;
        g_p4[j] = make_float4(x1, y1, x2, y2);
        g_pa[j] = (x2 - x1) * (y2 - y1);
        g_topv[j] = sigmoidf_(p[4]);
    }
}

// max IoU over all preds per target (division-free monotone q trick).
// blockIdx.y==0 blocks also do the per-pair DIoU + smooth-L1 partials.
__global__ void k_ioumax() {
    __shared__ float4 sp[PCHUNK];
    __shared__ float  sa[PCHUNK];
    int tid = threadIdx.x;
    int pbase = blockIdx.y * PCHUNK;
    for (int p = tid; p < PCHUNK; p += 128) {
        sp[p] = g_p4[pbase + p];
        sa[p] = g_pa[pbase + p];
    }
    __syncthreads();

    int t = blockIdx.x * 128 + tid;
    float4 T = g_t4[t];
    float ta = (T.z - T.x) * (T.w - T.y);
    float qb = 0.0f;
    #pragma unroll 4
    for (int p = 0; p < PCHUNK; p++) {
        float4 P = sp[p];            // broadcast LDS.128
        float ix1 = fmaxf(P.x, T.x);
        float iy1 = fmaxf(P.y, T.y);
        float ix2 = fminf(P.z, T.z);
        float iy2 = fminf(P.w, T.w);
        float w = fmaxf(ix2 - ix1, 0.0f);
        float h = fmaxf(iy2 - iy1, 0.0f);
        float inter = w * h;
        float s = sa[p] + ta;
        float q = inter * rcp_approx(s);
        qb = fmaxf(qb, q);
    }
    float iou = qb / (1.0f - qb);    // q in [0, 0.5] -> safe
    atomicMax(&g_miou[t], __float_as_int(iou));  // bits compare OK: iou >= 0

    if (blockIdx.y == 0) {
        // fused per-pair DIoU + smooth-L1 (pair index == t)
        float4 P = g_p4[t];
        float pa = fmaxf(P.z - P.x, 0.0f) * fmaxf(P.w - P.y, 0.0f);
        float tta = fmaxf(T.z - T.x, 0.0f) * fmaxf(T.w - T.y, 0.0f);
        float ix1 = fmaxf(P.x, T.x), iy1 = fmaxf(P.y, T.y);
        float ix2 = fminf(P.z, T.z), iy2 = fminf(P.w, T.w);
        float inter = fmaxf(ix2 - ix1, 0.0f) * fmaxf(iy2 - iy1, 0.0f);
        float iou2 = inter / (pa + tta - inter + 1e-7f);
        float dx = (P.x + P.z) * 0.5f - (T.x + T.z) * 0.5f;
        float dy = (P.y + P.w) * 0.5f - (T.y + T.w) * 0.5f;
        float cd = dx * dx + dy * dy;
        float gx = fmaxf(P.z, T.z) - fminf(P.x, T.x);
        float gy = fmaxf(P.w, T.w) - fminf(P.y, T.y);
        float diag = gx * gx + gy * gy;
        g_diou[t] = 1.0f - (iou2 - cd / (diag + 1e-7f));
        float c0 = P.x - T.x, c1 = P.y - T.y, c2 = P.z - T.z, c3 = P.w - T.w;
        float a0 = fabsf(c0), a1 = fabsf(c1), a2 = fabsf(c2), a3 = fabsf(c3);
        float sl = 0.0f;
        sl += (a0 < 1.0f) ? 0.5f * c0 * c0 : (a0 - 0.5f);
        sl += (a1 < 1.0f) ? 0.5f * c1 * c1 : (a1 - 0.5f);
        sl += (a2 < 1.0f) ? 0.5f * c2 * c2 : (a2 - 0.5f);
        sl += (a3 < 1.0f) ? 0.5f * c3 * c3 : (a3 - 0.5f);
        float tot = block_sum<4>(sl);
        if (tid == 0) g_sl1p[blockIdx.x] = tot;
    }
}

// Pairwise good-bad sum, with on-the-fly x/ac/bb (fused k_prep) and
// last-block final reduction (fused k_final).
__global__ void k_pairsum(float* __restrict__ out) {
    __shared__ float2 sac[256];
    __shared__ float  s_sl1;
    __shared__ bool   s_last;
    int tid = threadIdx.x;

    // total smooth-l1 from 50 partials
    float v = (tid < NIOUB) ? g_sl1p[tid] : 0.0f;
    float sv = block_sum<8>(v);
    if (tid == 0) s_sl1 = sv;
    __syncthreads();
    float sl1 = s_sl1 * (1.0f / (25600.0f * 512.0f));   // mean over N*4, /DESIRED_SIZE

    // ac row for this block's j-chunk
    int j = blockIdx.y * 256 + tid;
    float mi = fmaxf(__int_as_float(g_miou[j]), 0.0f);
    float x = 2.0f * (1.0f - mi) + g_diou[j] + sl1;
    sac[tid] = make_float2(x * x, (3.5f - x) * (3.5f - x));
    float y = g_topv[blockIdx.x * 256 + tid];
    float bb = (1.0f - y) * (1.0f - y);
    __syncthreads();

    float ag = 0.0f, ab = 0.0f;
    #pragma unroll 8
    for (int p = 0; p < 256; p++) {
        float2 acp = sac[p];         // broadcast LDS.64
        ag += sqrt_approx(acp.x + bb);
        ab += sqrt_approx(acp.y + bb);
    }
    float part = block_sum<8>(2.0f * ag - 1.5f * ab);
    if (tid == 0) {
        g_pairp[blockIdx.y * NPSB + blockIdx.x] = part;
        __threadfence();
        int t = atomicAdd(&g_ctr, 1);
        s_last = (t == NPSB * NPSB - 1);
    }
    __syncthreads();

    if (s_last) {
        // final reduction (all partials are globally visible now)
        double dp = 0.0, dn = 0.0;
        for (int i = tid; i < NPSB * NPSB; i += 256) dp += (double)g_pairp[i];
        for (int i = tid; i < CELLS / 256; i += 256) dn += (double)g_negp[i];
        // block reduce doubles
        #pragma unroll
        for (int o = 16; o > 0; o >>= 1) {
            dp += __shfl_down_sync(0xffffffffu, dp, o);
            dn += __shfl_down_sync(0xffffffffu, dn, o);
        }
        __shared__ double shp[8], shn[8];
        int lane = tid & 31, wid = tid >> 5;
        if (lane == 0) { shp[wid] = dp; shn[wid] = dn; }
        __syncthreads();
        if (tid == 0) {
            double tp = 0.0, tn = 0.0;
            #pragma unroll
            for (int w = 0; w < 8; w++) { tp += shp[w]; tn += shn[w]; }
            double mg = tp / ((double)NPAIR * (double)NPAIR);
            double l = mg + 5.25;
            if (l < 0.0) l = 0.0;
            out[0] = (float)(l + tn / (double)CELLS);
            g_ctr = 0;   // reset for next graph replay
        }
    }
}

// ---------------- launch ----------------
extern "C" void kernel_launch(void* const* d_in, const int* in_sizes, int n_in,
                              void* d_out, int out_size) {
    const float* pred = (const float*)d_in[0];   // [64,3,32,32,5]
    const float* tgt  = (const float*)d_in[1];   // [64,100,4]
    float* out = (float*)d_out;

    k_pre    <<<CELLS / 256, 256>>>(pred, tgt);
    k_topk   <<<BATCH, 256>>>(pred);
    k_ioumax <<<dim3(NIOUB, NPAIR / PCHUNK), 128>>>();
    k_pairsum<<<dim3(NPSB, NPSB), 256>>>(out);
}

// round 8
// speedup vs baseline: 1.0890x; 1.0890x over previous
#include <cuda_runtime.h>
#include <cstdint>
#include <cstddef>

// Problem constants
#define BATCH   64
#define CPB     3072           // anchors*H*W per batch (3*32*32)
#define CELLS   (BATCH*CPB)    // 196608
#define KSEL    100
#define NPAIR   (BATCH*KSEL)   // 6400
#define PCHUNK  320            // preds per IoU chunk (20 chunks)
#define NIOUB   (NPAIR/128)    // 50 iou blocks in x
#define NJT     50             // pairsum j-tiles (128 each)
#define NIT     25             // pairsum i-tiles (256 each)

// ---------------- scratch (device globals; no allocation) ----------------
__device__ float4 g_p4[NPAIR];        // selected pred corners
__device__ float  g_pa[NPAIR];        // pred areas
__device__ float4 g_t4[NPAIR];        // fixed target corners
__device__ float  g_topv[NPAIR];      // selected confidences
__device__ int    g_miou[NPAIR];      // max IoU per target (float bits, >=0)
__device__ float  g_diou[NPAIR];
__device__ float  g_negp[BATCH];      // negpen partials (per batch)
__device__ float  g_sl1p[NIOUB];      // smooth-l1 partials
__device__ float  g_pairp[NIT*NJT];   // 1250 pair partials
__device__ int    g_ctr;              // last-block counter (self-resetting)

// ---------------- helpers ----------------
__device__ __forceinline__ float rcp_approx(float x) {
    float y; asm("rcp.approx.f32 %0, %1;" : "=f"(y) : "f"(x)); return y;
}
__device__ __forceinline__ float sqrt_approx(float x) {
    float y; asm("sqrt.approx.f32 %0, %1;" : "=f"(y) : "f"(x)); return y;
}
__device__ __forceinline__ float sigmoidf_(float x) {
    return 1.0f / (1.0f + expf(-x));
}

// full-block float sum, result valid in thread 0 (NW warps)
template<int NW>
__device__ __forceinline__ float block_sum(float v) {
    __shared__ float sh[NW];
    #pragma unroll
    for (int o = 16; o > 0; o >>= 1) v += __shfl_down_sync(0xffffffffu, v, o);
    int lane = threadIdx.x & 31, wid = threadIdx.x >> 5;
    if (lane == 0) sh[wid] = v;
    __syncthreads();
    float s = 0.0f;
    if (wid == 0) {
        s = (lane < NW) ? sh[lane] : 0.0f;
        #pragma unroll
        for (int o = NW / 2; o > 0; o >>= 1) s += __shfl_down_sync(0xffffffffu, s, o);
    }
    __syncthreads();   // safe smem reuse by later calls
    return s;
}

// ---------------- kernels ----------------

// One block per batch: stream pred through smem (coalesced float4), build
// order-preserving conf keys in smem, negpen partial, fix this batch's 100
// targets, then radix-select + bitonic sort for exact jax.top_k ordering
// (descending conf, ties -> smaller index via index complement).
__global__ void k_topk(const float* __restrict__ pred, const float* __restrict__ tgt) {
    __shared__ float4 buf[320];                 // 5KB staging (256 cells)
    __shared__ unsigned int keys[CPB];          // 12KB
    __shared__ unsigned int hist[4096];         // 16KB
    __shared__ unsigned long long cand[512];    // 4KB
    __shared__ unsigned int tsum[256];
    __shared__ unsigned int safter[256];
    __shared__ unsigned int s_cnt, s_pivot;

    int b = blockIdx.x;
    int tid = threadIdx.x;

    for (int i = tid; i < 4096; i += 256) hist[i] = 0;
    if (tid == 0) s_cnt = 0;

    // fix this batch's 100 targets + init miou (independent of smem flow)
    if (tid < KSEL) {
        int j = b * KSEL + tid;
        g_miou[j] = 0;
        const float* t = tgt + (size_t)j * 4;
        float a = t[0], b2 = t[1], c = t[2], d = t[3];
        float x1 = fminf(a, c), x2 = fmaxf(a, c);
        float y1 = fminf(b2, d), y2 = fmaxf(b2, d);
        if (x1 == x2) x2 = x1 + 1.0f;
        if (y1 == y2) y2 = y1 + 1.0f;
        g_t4[j] = make_float4(x1, y1, x2, y2);
    }

    // stream 3072 cells in 12 chunks of 256 cells (320 float4)
    const float4* src = (const float4*)(pred + (size_t)b * CPB * 5);
    float neg = 0.0f;
    for (int c = 0; c < 12; c++) {
        __syncthreads();                       // covers hist init + buf reuse
        #pragma unroll 2
        for (int i = tid; i < 320; i += 256) buf[i] = src[c * 320 + i];
        __syncthreads();
        const float* f = (const float*)buf;
        float pw = f[tid * 5 + 2], ph = f[tid * 5 + 3], cl = f[tid * 5 + 4];
        neg += fmaxf(1.0f - pw, 0.0f) + fmaxf(1.0f - ph, 0.0f);
        unsigned int u = __float_as_uint(cl);
        u = (u & 0x80000000u) ? ~u : (u | 0x80000000u);   // order-preserving
        keys[c * 256 + tid] = u;
        atomicAdd(&hist[u >> 20], 1u);
    }
    float tot = block_sum<8>(neg);
    if (tid == 0) g_negp[b] = tot;
    __syncthreads();

    // suffix counts over 4096 buckets
    unsigned int mysum = 0;
    #pragma unroll
    for (int q = 0; q < 16; q++) mysum += hist[tid * 16 + q];
    tsum[tid] = mysum;
    __syncthreads();
    if (tid == 0) {
        unsigned int acc = 0;
        for (int t = 255; t >= 0; t--) { safter[t] = acc; acc += tsum[t]; }
    }
    __syncthreads();

    // pivot = max bucket with suffix-count >= KSEL (exactly one thread finds it)
    {
        unsigned int run = safter[tid];
        for (int q = 15; q >= 0; q--) {
            unsigned int c = hist[tid * 16 + q];
            run += c;
            if (run >= KSEL && (run - c) < KSEL) s_pivot = tid * 16 + q;
        }
    }
    __syncthreads();
    unsigned int piv = s_pivot;

    // gather candidates (all buckets >= pivot)
    #pragma unroll 4
    for (int s = tid; s < CPB; s += 256) {
        unsigned int u = keys[s];
        if ((u >> 20) >= piv) {
            unsigned int pos = atomicAdd(&s_cnt, 1u);
            if (pos < 512)
                cand[pos] = ((unsigned long long)u << 32) |
                            (unsigned long long)(0xFFFFFFFFu - (unsigned int)s);
        }
    }
    __syncthreads();
    unsigned int cnt = s_cnt; if (cnt > 512) cnt = 512;
    for (int i = tid; i < 512; i += 256) if (i >= (int)cnt) cand[i] = 0ull;

    // bitonic sort 512, descending
    for (unsigned int k = 2; k <= 512; k <<= 1) {
        for (unsigned int j = k >> 1; j > 0; j >>= 1) {
            __syncthreads();
            #pragma unroll 2
            for (int i = tid; i < 512; i += 256) {
                unsigned int ixj = (unsigned int)i ^ j;
                if (ixj > (unsigned int)i) {
                    unsigned long long a = cand[i], c2 = cand[ixj];
                    bool up = (((unsigned int)i & k) == 0);
                    if ((a < c2) == up) { cand[i] = c2; cand[ixj] = a; }
                }
            }
        }
    }
    __syncthreads();

    // winners -> postprocessed pred corners
    if (tid < KSEL) {
        unsigned long long m = cand[tid];
        int idx = (int)(0xFFFFFFFFu - (unsigned int)(m & 0xFFFFFFFFull));
        int j = b * KSEL + tid;
        const float* p = pred + (size_t)b * CPB * 5 + (size_t)idx * 5;
        float x = (sigmoidf_(p[0]) + (float)(idx & 31)) * 32.0f;         // + cx, *STRIDE
        float y = (sigmoidf_(p[1]) + (float)((idx >> 5) & 31)) * 32.0f;  // + cy
        float hw = expf(p[2]) * 32.0f * 0.5f;
        float hh = expf(p[3]) * 32.0f * 0.5f;
        float x1 = x - hw, y1 = y - hh, x2 = x + hw, y2 = y + hh;
        g_p4[j] = make_float4(x1, y1, x2, y2);
        g_pa[j] = (x2 - x1) * (y2 - y1);
        g_topv[j] = sigmoidf_(p[4]);
    }
}

// max IoU over all preds per target (division-free monotone q trick).
// 1000 blocks (50 x 20) for wave balance. blockIdx.y==0 also does the
// per-pair DIoU + smooth-L1 partials.
__global__ void k_ioumax() {
    __shared__ float4 sp[PCHUNK];
    __shared__ float  sa[PCHUNK];
    int tid = threadIdx.x;
    int pbase = blockIdx.y * PCHUNK;
    for (int p = tid; p < PCHUNK; p += 128) {
        sp[p] = g_p4[pbase + p];
        sa[p] = g_pa[pbase + p];
    }
    __syncthreads();

    int t = blockIdx.x * 128 + tid;
    float4 T = g_t4[t];
    float ta = (T.z - T.x) * (T.w - T.y);
    float qb = 0.0f;
    #pragma unroll 4
    for (int p = 0; p < PCHUNK; p++) {
        float4 P = sp[p];            // broadcast LDS.128
        float ix1 = fmaxf(P.x, T.x);
        float iy1 = fmaxf(P.y, T.y);
        float ix2 = fminf(P.z, T.z);
        float iy2 = fminf(P.w, T.w);
        float w = fmaxf(ix2 - ix1, 0.0f);
        float h = fmaxf(iy2 - iy1, 0.0f);
        float inter = w * h;
        float s = sa[p] + ta;
        float q = inter * rcp_approx(s);
        qb = fmaxf(qb, q);
    }
    float iou = qb / (1.0f - qb);    // q in [0, 0.5] -> safe
    atomicMax(&g_miou[t], __float_as_int(iou));  // bits compare OK: iou >= 0

    if (blockIdx.y == 0) {
        // fused per-pair DIoU + smooth-L1 (pair index == t)
        float4 P = g_p4[t];
        float pa = fmaxf(P.z - P.x, 0.0f) * fmaxf(P.w - P.y, 0.0f);
        float tta = fmaxf(T.z - T.x, 0.0f) * fmaxf(T.w - T.y, 0.0f);
        float ix1 = fmaxf(P.x, T.x), iy1 = fmaxf(P.y, T.y);
        float ix2 = fminf(P.z, T.z), iy2 = fminf(P.w, T.w);
        float inter = fmaxf(ix2 - ix1, 0.0f) * fmaxf(iy2 - iy1, 0.0f);
        float iou2 = inter / (pa + tta - inter + 1e-7f);
        float dx = (P.x + P.z) * 0.5f - (T.x + T.z) * 0.5f;
        float dy = (P.y + P.w) * 0.5f - (T.y + T.w) * 0.5f;
        float cd = dx * dx + dy * dy;
        float gx = fmaxf(P.z, T.z) - fminf(P.x, T.x);
        float gy = fmaxf(P.w, T.w) - fminf(P.y, T.y);
        float diag = gx * gx + gy * gy;
        g_diou[t] = 1.0f - (iou2 - cd / (diag + 1e-7f));
        float c0 = P.x - T.x, c1 = P.y - T.y, c2 = P.z - T.z, c3 = P.w - T.w;
        float a0 = fabsf(c0), a1 = fabsf(c1), a2 = fabsf(c2), a3 = fabsf(c3);
        float sl = 0.0f;
        sl += (a0 < 1.0f) ? 0.5f * c0 * c0 : (a0 - 0.5f);
        sl += (a1 < 1.0f) ? 0.5f * c1 * c1 : (a1 - 0.5f);
        sl += (a2 < 1.0f) ? 0.5f * c2 * c2 : (a2 - 0.5f);
        sl += (a3 < 1.0f) ? 0.5f * c3 * c3 : (a3 - 0.5f);
        float tot = block_sum<4>(sl);
        if (tid == 0) g_sl1p[blockIdx.x] = tot;
    }
}

// Pairwise good-bad sum, tiles 256(i) x 128(j) -> 1250 blocks for balance.
// On-the-fly ac/bb; last block does the final reduction.
__global__ void k_pairsum(float* __restrict__ out) {
    __shared__ float4 sac4[64];          // 128 float2 (a_j, c_j)
    __shared__ float  s_sl1;
    __shared__ bool   s_last;
    int tid = threadIdx.x;

    // total smooth-l1 from 50 partials
    float v = (tid < NIOUB) ? g_sl1p[tid] : 0.0f;
    float sv = block_sum<8>(v);
    if (tid == 0) s_sl1 = sv;
    __syncthreads();
    float sl1 = s_sl1 * (1.0f / (25600.0f * 512.0f));   // mean over N*4, /DESIRED_SIZE

    // ac for this block's 128-j tile
    if (tid < 128) {
        int j = blockIdx.x * 128 + tid;
        float mi = fmaxf(__int_as_float(g_miou[j]), 0.0f);
        float x = 2.0f * (1.0f - mi) + g_diou[j] + sl1;
        ((float2*)sac4)[tid] = make_float2(x * x, (3.5f - x) * (3.5f - x));
    }
    int i = blockIdx.y * 256 + tid;
    float y = g_topv[i];
    float bb = (1.0f - y) * (1.0f - y);
    __syncthreads();

    float ag = 0.0f, ab = 0.0f;
    #pragma unroll 8
    for (int p = 0; p < 64; p++) {
        float4 w = sac4[p];              // broadcast LDS.128: two (a,c) pairs
        ag += sqrt_approx(w.x + bb);
        ab += sqrt_approx(w.y + bb);
        ag += sqrt_approx(w.z + bb);
        ab += sqrt_approx(w.w + bb);
    }
    float part = block_sum<8>(2.0f * ag - 1.5f * ab);
    if (tid == 0) {
        g_pairp[blockIdx.y * NJT + blockIdx.x] = part;
        __threadfence();
        int t = atomicAdd(&g_ctr, 1);
        s_last = (t == NIT * NJT - 1);
    }
    __syncthreads();

    if (s_last) {
        double dp = 0.0, dn = 0.0;
        for (int k = tid; k < NIT * NJT; k += 256) dp += (double)g_pairp[k];
        for (int k = tid; k < BATCH; k += 256) dn += (double)g_negp[k];
        #pragma unroll
        for (int o = 16; o > 0; o >>= 1) {
            dp += __shfl_down_sync(0xffffffffu, dp, o);
            dn += __shfl_down_sync(0xffffffffu, dn, o);
        }
        __shared__ double shp[8], shn[8];
        int lane = tid & 31, wid = tid >> 5;
        if (lane == 0) { shp[wid] = dp; shn[wid] = dn; }
        __syncthreads();
        if (tid == 0) {
            double tp = 0.0, tn = 0.0;
            #pragma unroll
            for (int w = 0; w < 8; w++) { tp += shp[w]; tn += shn[w]; }
            double mg = tp / ((double)NPAIR * (double)NPAIR);
            double l = mg + 5.25;
            if (l < 0.0) l = 0.0;
            out[0] = (float)(l + tn / (double)CELLS);
            g_ctr = 0;   // reset for next graph replay
        }
    }
}

// ---------------- launch ----------------
extern "C" void kernel_launch(void* const* d_in, const int* in_sizes, int n_in,
                              void* d_out, int out_size) {
    const float* pred = (const float*)d_in[0];   // [64,3,32,32,5]
    const float* tgt  = (const float*)d_in[1];   // [64,100,4]
    float* out = (float*)d_out;

    k_topk   <<<BATCH, 256>>>(pred, tgt);
    k_ioumax <<<dim3(NIOUB, NPAIR / PCHUNK), 128>>>();
    k_pairsum<<<dim3(NJT, NIT), 256>>>(out);
}

// round 9
// speedup vs baseline: 1.2350x; 1.1341x over previous
#include <cuda_runtime.h>
#include <cstdint>
#include <cstddef>

// Problem constants
#define BATCH   64
#define CPB     3072           // anchors*H*W per batch (3*32*32)
#define CELLS   (BATCH*CPB)    // 196608
#define KSEL    100
#define NPAIR   (BATCH*KSEL)   // 6400
#define PCHUNK  320            // preds per IoU chunk (20 chunks)
#define NIOUB   (NPAIR/128)    // 50 iou blocks in x
#define NJT     50             // pairsum j-tiles (128 each)
#define NIT     25             // pairsum i-tiles (256 each)
#define TKT     512            // topk threads

// ---------------- scratch (device globals; no allocation) ----------------
__device__ float4 g_p4[NPAIR];        // selected pred corners
__device__ float  g_pa[NPAIR];        // pred areas
__device__ float4 g_t4[NPAIR];        // fixed target corners
__device__ float  g_topv[NPAIR];      // selected confidences
__device__ int    g_miou[NPAIR];      // max IoU per target (float bits, >=0)
__device__ float  g_diou[NPAIR];
__device__ float  g_negp[BATCH];      // negpen partials (per batch)
__device__ float  g_sl1p[NIOUB];      // smooth-l1 partials
__device__ float  g_pairp[NIT*NJT];   // 1250 pair partials
__device__ int    g_ctr;              // last-block counter (self-resetting)

// ---------------- helpers ----------------
__device__ __forceinline__ float rcp_approx(float x) {
    float y; asm("rcp.approx.f32 %0, %1;" : "=f"(y) : "f"(x)); return y;
}
__device__ __forceinline__ float sqrt_approx(float x) {
    float y; asm("sqrt.approx.f32 %0, %1;" : "=f"(y) : "f"(x)); return y;
}
// fma-pipe sqrt: magic rsqrt seed + 2 Newton iters (rel err ~4e-6; x >= ~1e-4)
__device__ __forceinline__ float sqrt_newton(float d) {
    float x = __uint_as_float(0x5f3759dfu - (__float_as_uint(d) >> 1));
    x = x * (1.5f - 0.5f * d * x * x);
    x = x * (1.5f - 0.5f * d * x * x);
    return d * x;
}
__device__ __forceinline__ float sigmoidf_(float x) {
    return 1.0f / (1.0f + expf(-x));
}

// full-block float sum, result valid in thread 0 (NW warps)
template<int NW>
__device__ __forceinline__ float block_sum(float v) {
    __shared__ float sh[NW];
    #pragma unroll
    for (int o = 16; o > 0; o >>= 1) v += __shfl_down_sync(0xffffffffu, v, o);
    int lane = threadIdx.x & 31, wid = threadIdx.x >> 5;
    if (lane == 0) sh[wid] = v;
    __syncthreads();
    float s = 0.0f;
    if (wid == 0) {
        s = (lane < NW) ? sh[lane] : 0.0f;
        #pragma unroll
        for (int o = NW / 2; o > 0; o >>= 1) s += __shfl_down_sync(0xffffffffu, s, o);
    }
    __syncthreads();   // safe smem reuse by later calls
    return s;
}

// ---------------- kernels ----------------

// One 512-thread block per batch: single-pass key build (no staging),
// negpen partial, target fix, 12-bit radix-select, hybrid shfl/smem bitonic.
__global__ void __launch_bounds__(TKT) k_topk(const float* __restrict__ pred,
                                              const float* __restrict__ tgt) {
    __shared__ unsigned int keys[CPB];          // 12KB
    __shared__ unsigned int hist[4096];         // 16KB
    __shared__ unsigned long long cand[512];    // 4KB
    __shared__ unsigned int tsum[256];
    __shared__ unsigned int safter[256];
    __shared__ unsigned int wsum[8];
    __shared__ unsigned int s_cnt, s_pivot;

    int b = blockIdx.x;
    int tid = threadIdx.x;
    int lane = tid & 31, wid = tid >> 5;

    for (int i = tid; i < 4096; i += TKT) hist[i] = 0;
    if (tid == 0) s_cnt = 0;

    // fix this batch's 100 targets + init miou
    if (tid < KSEL) {
        int j = b * KSEL + tid;
        g_miou[j] = 0;
        const float* t = tgt + (size_t)j * 4;
        float a = t[0], b2 = t[1], c = t[2], d = t[3];
        float x1 = fminf(a, c), x2 = fmaxf(a, c);
        float y1 = fminf(b2, d), y2 = fmaxf(b2, d);
        if (x1 == x2) x2 = x1 + 1.0f;
        if (y1 == y2) y2 = y1 + 1.0f;
        g_t4[j] = make_float4(x1, y1, x2, y2);
    }
    __syncthreads();   // hist zeroed before atomics

    // one coalesced pass: decode role per component, build keys + negpen
    const float4* src = (const float4*)(pred + (size_t)b * CPB * 5);
    float neg = 0.0f;
    for (int f = tid; f < CPB * 5 / 4; f += TKT) {
        float4 q4 = src[f];
        float vals[4] = {q4.x, q4.y, q4.z, q4.w};
        int e0 = 4 * f;
        #pragma unroll
        for (int m = 0; m < 4; m++) {
            int e = e0 + m;
            int cell = e / 5;
            int role = e - cell * 5;
            float v = vals[m];
            if (role == 2 || role == 3) {
                neg += fmaxf(1.0f - v, 0.0f);
            } else if (role == 4) {
                unsigned int u = __float_as_uint(v);
                u = (u & 0x80000000u) ? ~u : (u | 0x80000000u);  // order-preserving
                keys[cell] = u;
                atomicAdd(&hist[u >> 20], 1u);
            }
        }
    }
    float tot = block_sum<16>(neg);
    if (tid == 0) g_negp[b] = tot;
    __syncthreads();

    // parallel suffix scan over 4096 buckets (16/thread, 256 threads)
    unsigned int sv = 0;
    if (tid < 256) {
        unsigned int s0 = 0;
        #pragma unroll
        for (int q = 0; q < 16; q++) s0 += hist[tid * 16 + q];
        tsum[tid] = s0;
        sv = s0;
        #pragma unroll
        for (int o = 1; o < 32; o <<= 1) {
            unsigned int t = __shfl_down_sync(0xffffffffu, sv, o);
            if (lane + o < 32) sv += t;           // in-warp inclusive suffix
        }
        if (lane == 0) wsum[wid] = sv;            // warp total
    }
    __syncthreads();
    if (tid < 256) {
        unsigned int hi = 0;
        #pragma unroll
        for (int w = 0; w < 8; w++) if (w > wid) hi += wsum[w];
        safter[tid] = sv + hi - tsum[tid];        // exclusive suffix (strictly above)
        // pivot = max bucket whose suffix-count crosses KSEL
        unsigned int run = safter[tid];
        for (int q = 15; q >= 0; q--) {
            unsigned int c = hist[tid * 16 + q];
            run += c;
            if (run >= KSEL && (run - c) < KSEL) s_pivot = tid * 16 + q;
        }
    }
    __syncthreads();
    unsigned int piv = s_pivot;

    // gather candidates (buckets >= pivot); unique 64-bit keys
    for (int s = tid; s < CPB; s += TKT) {
        unsigned int u = keys[s];
        if ((u >> 20) >= piv) {
            unsigned int pos = atomicAdd(&s_cnt, 1u);
            if (pos < 512)
                cand[pos] = ((unsigned long long)u << 32) |
                            (unsigned long long)(0xFFFFFFFFu - (unsigned int)s);
        }
    }
    __syncthreads();
    unsigned int cnt = s_cnt; if (cnt > 512) cnt = 512;
    if (tid >= (int)cnt) cand[tid] = 0ull;
    __syncthreads();

    // hybrid bitonic sort (descending): 1 elem/thread in register,
    // shfl_xor for j<=16 stages, smem only for j>=32.
    unsigned long long v = cand[tid];
    #pragma unroll
    for (unsigned int k = 2; k <= 32; k <<= 1) {
        #pragma unroll
        for (unsigned int j = k >> 1; j > 0; j >>= 1) {
            unsigned long long t = __shfl_xor_sync(0xffffffffu, v, j);
            bool keep_max = (((tid & j) == 0) == ((tid & k) == 0));
            v = (keep_max == (v > t)) ? v : t;
        }
    }
    #pragma unroll
    for (unsigned int k = 64; k <= 512; k <<= 1) {
        for (unsigned int j = k >> 1; j >= 32; j >>= 1) {
            cand[tid] = v;
            __syncthreads();
            unsigned long long t = cand[tid ^ j];
            bool keep_max = (((tid & j) == 0) == ((tid & k) == 0));
            v = (keep_max == (v > t)) ? v : t;
            __syncthreads();
        }
        #pragma unroll
        for (unsigned int j = 16; j > 0; j >>= 1) {
            unsigned long long t = __shfl_xor_sync(0xffffffffu, v, j);
            bool keep_max = (((tid & j) == 0) == ((tid & k) == 0));
            v = (keep_max == (v > t)) ? v : t;
        }
    }
    cand[tid] = v;
    __syncthreads();

    // winners -> postprocessed pred corners
    if (tid < KSEL) {
        unsigned long long m = cand[tid];
        int idx = (int)(0xFFFFFFFFu - (unsigned int)(m & 0xFFFFFFFFull));
        int j = b * KSEL + tid;
        const float* p = pred + (size_t)b * CPB * 5 + (size_t)idx * 5;
        float x = (sigmoidf_(p[0]) + (float)(idx & 31)) * 32.0f;         // + cx, *STRIDE
        float y = (sigmoidf_(p[1]) + (float)((idx >> 5) & 31)) * 32.0f;  // + cy
        float hw = expf(p[2]) * 32.0f * 0.5f;
        float hh = expf(p[3]) * 32.0f * 0.5f;
        float x1 = x - hw, y1 = y - hh, x2 = x + hw, y2 = y + hh;
        g_p4[j] = make_float4(x1, y1, x2, y2);
        g_pa[j] = (x2 - x1) * (y2 - y1);
        g_topv[j] = sigmoidf_(p[4]);
    }
}

// max IoU over all preds per target (division-free monotone q trick).
// 1000 blocks (50 x 20). blockIdx.y==0 also does DIoU + smooth-L1 partials.
__global__ void k_ioumax() {
    __shared__ float4 sp[PCHUNK];
    __shared__ float  sa[PCHUNK];
    int tid = threadIdx.x;
    int pbase = blockIdx.y * PCHUNK;
    for (int p = tid; p < PCHUNK; p += 128) {
        sp[p] = g_p4[pbase + p];
        sa[p] = g_pa[pbase + p];
    }
    __syncthreads();

    int t = blockIdx.x * 128 + tid;
    float4 T = g_t4[t];
    float ta = (T.z - T.x) * (T.w - T.y);
    float qb = 0.0f;
    #pragma unroll 4
    for (int p = 0; p < PCHUNK; p++) {
        float4 P = sp[p];            // broadcast LDS.128
        float ix1 = fmaxf(P.x, T.x);
        float iy1 = fmaxf(P.y, T.y);
        float ix2 = fminf(P.z, T.z);
        float iy2 = fminf(P.w, T.w);
        float w = fmaxf(ix2 - ix1, 0.0f);
        float h = fmaxf(iy2 - iy1, 0.0f);
        float inter = w * h;
        float s = sa[p] + ta;
        float q = inter * rcp_approx(s);
        qb = fmaxf(qb, q);
    }
    float iou = qb / (1.0f - qb);    // q in [0, 0.5] -> safe
    atomicMax(&g_miou[t], __float_as_int(iou));  // bits compare OK: iou >= 0

    if (blockIdx.y == 0) {
        float4 P = g_p4[t];
        float pa = fmaxf(P.z - P.x, 0.0f) * fmaxf(P.w - P.y, 0.0f);
        float tta = fmaxf(T.z - T.x, 0.0f) * fmaxf(T.w - T.y, 0.0f);
        float ix1 = fmaxf(P.x, T.x), iy1 = fmaxf(P.y, T.y);
        float ix2 = fminf(P.z, T.z), iy2 = fminf(P.w, T.w);
        float inter = fmaxf(ix2 - ix1, 0.0f) * fmaxf(iy2 - iy1, 0.0f);
        float iou2 = inter / (pa + tta - inter + 1e-7f);
        float dx = (P.x + P.z) * 0.5f - (T.x + T.z) * 0.5f;
        float dy = (P.y + P.w) * 0.5f - (T.y + T.w) * 0.5f;
        float cd = dx * dx + dy * dy;
        float gx = fmaxf(P.z, T.z) - fminf(P.x, T.x);
        float gy = fmaxf(P.w, T.w) - fminf(P.y, T.y);
        float diag = gx * gx + gy * gy;
        g_diou[t] = 1.0f - (iou2 - cd / (diag + 1e-7f));
        float c0 = P.x - T.x, c1 = P.y - T.y, c2 = P.z - T.z, c3 = P.w - T.w;
        float a0 = fabsf(c0), a1 = fabsf(c1), a2 = fabsf(c2), a3 = fabsf(c3);
        float sl = 0.0f;
        sl += (a0 < 1.0f) ? 0.5f * c0 * c0 : (a0 - 0.5f);
        sl += (a1 < 1.0f) ? 0.5f * c1 * c1 : (a1 - 0.5f);
        sl += (a2 < 1.0f) ? 0.5f * c2 * c2 : (a2 - 0.5f);
        sl += (a3 < 1.0f) ? 0.5f * c3 * c3 : (a3 - 0.5f);
        float tot = block_sum<4>(sl);
        if (tid == 0) g_sl1p[blockIdx.x] = tot;
    }
}

// Pairwise good-bad sum, 256(i) x 128(j) tiles -> 1250 blocks.
// MUFU/fma balance: every 3rd j-pair's "bad" sqrts go through the fma pipe.
__global__ void k_pairsum(float* __restrict__ out) {
    __shared__ float4 sac4[64];          // 128 (a_j, c_j) pairs
    __shared__ float  s_sl1;
    __shared__ bool   s_last;
    int tid = threadIdx.x;

    // total smooth-l1 from 50 partials
    float v = (tid < NIOUB) ? g_sl1p[tid] : 0.0f;
    float sv = block_sum<8>(v);
    if (tid == 0) s_sl1 = sv;
    __syncthreads();
    float sl1 = s_sl1 * (1.0f / (25600.0f * 512.0f));   // mean over N*4, /DESIRED_SIZE

    if (tid < 128) {
        int j = blockIdx.x * 128 + tid;
        float mi = fmaxf(__int_as_float(g_miou[j]), 0.0f);
        float x = 2.0f * (1.0f - mi) + g_diou[j] + sl1;
        ((float2*)sac4)[tid] = make_float2(x * x, (3.5f - x) * (3.5f - x));
    }
    int i = blockIdx.y * 256 + tid;
    float y = g_topv[i];
    float bb = (1.0f - y) * (1.0f - y);
    __syncthreads();

    float ag = 0.0f, ab = 0.0f;
    #pragma unroll 6
    for (int p = 0; p < 64; p++) {
        float4 w = sac4[p];              // two (a,c) pairs
        ag += sqrt_approx(w.x + bb);
        ag += sqrt_approx(w.z + bb);
        if (p % 3 == 0) {                // 1/6 of all sqrts via fma pipe
            ab += sqrt_newton(w.y + bb);
            ab += sqrt_newton(w.w + bb);
        } else {
            ab += sqrt_approx(w.y + bb);
            ab += sqrt_approx(w.w + bb);
        }
    }
    float part = block_sum<8>(2.0f * ag - 1.5f * ab);
    if (tid == 0) {
        g_pairp[blockIdx.y * NJT + blockIdx.x] = part;
        __threadfence();
        int t = atomicAdd(&g_ctr, 1);
        s_last = (t == NIT * NJT - 1);
    }
    __syncthreads();

    if (s_last) {
        double dp = 0.0, dn = 0.0;
        for (int k = tid; k < NIT * NJT; k += 256) dp += (double)g_pairp[k];
        for (int k = tid; k < BATCH; k += 256) dn += (double)g_negp[k];
        #pragma unroll
        for (int o = 16; o > 0; o >>= 1) {
            dp += __shfl_down_sync(0xffffffffu, dp, o);
            dn += __shfl_down_sync(0xffffffffu, dn, o);
        }
        __shared__ double shp[8], shn[8];
        int lane = tid & 31, wid = tid >> 5;
        if (lane == 0) { shp[wid] = dp; shn[wid] = dn; }
        __syncthreads();
        if (tid == 0) {
            double tp = 0.0, tn = 0.0;
            #pragma unroll
            for (int w = 0; w < 8; w++) { tp += shp[w]; tn += shn[w]; }
            double mg = tp / ((double)NPAIR * (double)NPAIR);
            double l = mg + 5.25;
            if (l < 0.0) l = 0.0;
            out[0] = (float)(l + tn / (double)CELLS);
            g_ctr = 0;   // reset for next graph replay
        }
    }
}

// ---------------- launch ----------------
extern "C" void kernel_launch(void* const* d_in, const int* in_sizes, int n_in,
                              void* d_out, int out_size) {
    const float* pred = (const float*)d_in[0];   // [64,3,32,32,5]
    const float* tgt  = (const float*)d_in[1];   // [64,100,4]
    float* out = (float*)d_out;

    k_topk   <<<BATCH, TKT>>>(pred, tgt);
    k_ioumax <<<dim3(NIOUB, NPAIR / PCHUNK), 128>>>();
    k_pairsum<<<dim3(NJT, NIT), 256>>>(out);
}